// round 6
// baseline (speedup 1.0000x reference)
#include <cuda_runtime.h>
#include <cuda_bf16.h>
#include <cstdint>

#define DEV __device__ __forceinline__

constexpr int NB = 8;
constexpr int C  = 64;
constexpr int L  = 4096;
constexpr int BR = 128;           // query rows per CTA
constexpr int BC = 64;           // keys per iteration
constexpr int NIT = L / BC;       // 64

// fp8 e4m3 scratch. Q,K: [B,L,C] natural order (64B rows).
// V: [B,C,L] channel-major with key-bytes sigma-permuted within 16-blocks.
__device__ uint8_t g_Q[NB * L * C];
__device__ uint8_t g_K[NB * L * C];
__device__ uint8_t g_V[NB * L * C];

DEV uint32_t smem_u32(const void* p) { return (uint32_t)__cvta_generic_to_shared(p); }
DEV uint32_t swz64(uint32_t o) { return o ^ ((o >> 3) & 0x30); }   // SW64: 64B rows

DEV float fast_exp2(float x) { float r; asm("ex2.approx.ftz.f32 %0, %1;" : "=f"(r) : "f"(x)); return r; }
DEV float fast_rcp (float x) { float r; asm("rcp.approx.ftz.f32 %0, %1;" : "=f"(r) : "f"(x)); return r; }

DEV void cp16(uint32_t dst, const void* src) {
    asm volatile("cp.async.cg.shared.global [%0], [%1], 16;\n" :: "r"(dst), "l"(src));
}
DEV void cp_commit() { asm volatile("cp.async.commit_group;\n"); }
template<int N> DEV void cp_wait() { asm volatile("cp.async.wait_group %0;\n" :: "n"(N)); }

DEV void ldsm_x4(uint32_t& r0, uint32_t& r1, uint32_t& r2, uint32_t& r3, uint32_t a) {
    asm volatile("ldmatrix.sync.aligned.m8n8.x4.shared.b16 {%0,%1,%2,%3}, [%4];"
        : "=r"(r0), "=r"(r1), "=r"(r2), "=r"(r3) : "r"(a));
}
// fp8 e4m3 MMA: D(16x8 f32) += A(16x32 e4m3) * B(32x8 e4m3)
DEV void mma_fp8(float& c0, float& c1, float& c2, float& c3,
                 uint32_t a0, uint32_t a1, uint32_t a2, uint32_t a3,
                 uint32_t b0, uint32_t b1) {
    asm volatile("mma.sync.aligned.m16n8k32.row.col.f32.e4m3.e4m3.f32 "
        "{%0,%1,%2,%3}, {%4,%5,%6,%7}, {%8,%9}, {%0,%1,%2,%3};"
        : "+f"(c0), "+f"(c1), "+f"(c2), "+f"(c3)
        : "r"(a0), "r"(a1), "r"(a2), "r"(a3), "r"(b0), "r"(b1));
}
// pack two f32 -> e4m3x2 (lo in byte0, hi in byte1)
DEV uint16_t pk_e4(float lo, float hi) {
    uint16_t r;
    asm("cvt.rn.satfinite.e4m3x2.f32 %0, %1, %2;" : "=h"(r) : "f"(hi), "f"(lo));
    return r;
}
DEV uint8_t e4(float v) { return (uint8_t)pk_e4(v, 0.f); }

// ---------------------------------------------------------------------------
// Kernel A: QKV projection -> fp8.  Q,K natural [B,L,C]; V transposed [B,C,L]
// with sigma key-permutation (within each 16-key block) for shuffle-free P frags.
// ---------------------------------------------------------------------------
__global__ void __launch_bounds__(256) qkv_kernel(
    const float* __restrict__ x,
    const float* __restrict__ Wq, const float* __restrict__ bq,
    const float* __restrict__ Wk, const float* __restrict__ bk,
    const float* __restrict__ Wv, const float* __restrict__ bv)
{
    __shared__ __nv_bfloat16 Ws[3][64][66];
    __shared__ __align__(16) float xs[64][64];

    const int b    = blockIdx.x >> 6;
    const int tile = blockIdx.x & 63;
    const int l0   = tile * 64;
    const int tid  = threadIdx.x;

    for (int idx = tid; idx < 4096; idx += 256) {
        int r = idx >> 6, cc = idx & 63;
        Ws[0][r][cc] = __float2bfloat16(Wq[idx]);
        Ws[1][r][cc] = __float2bfloat16(Wk[idx]);
        Ws[2][r][cc] = __float2bfloat16(Wv[idx]);
    }
    for (int idx = tid; idx < 4096; idx += 256) {
        int cp = idx >> 6, j = idx & 63;
        xs[cp][j] = x[(size_t)(b * 64 + cp) * 4096 + l0 + j];
    }
    __syncthreads();

    const int c = tid & 63;
    const int g = tid >> 6;

    float a0[16], a1[16], a2[16];
    const float bqv = bq[c], bkv = bk[c], bvv = bv[c];
    #pragma unroll
    for (int j = 0; j < 16; j++) { a0[j] = bqv; a1[j] = bkv; a2[j] = bvv; }

    #pragma unroll 4
    for (int cp = 0; cp < 64; cp++) {
        float wq = __bfloat162float(Ws[0][c][cp]);
        float wk = __bfloat162float(Ws[1][c][cp]);
        float wv = __bfloat162float(Ws[2][c][cp]);
        const float4* xr = reinterpret_cast<const float4*>(&xs[cp][g * 16]);
        float4 xv4[4];
        #pragma unroll
        for (int q4 = 0; q4 < 4; q4++) xv4[q4] = xr[q4];
        const float* xv = reinterpret_cast<const float*>(xv4);
        #pragma unroll
        for (int j = 0; j < 16; j++) {
            a0[j] += wq * xv[j];
            a1[j] += wk * xv[j];
            a2[j] += wv * xv[j];
        }
    }

    // Q, K: natural scale fp8 (scale applied post-MMA in attention)
    #pragma unroll
    for (int j = 0; j < 16; j++) {
        int l = l0 + g * 16 + j;
        size_t o = ((size_t)b * 4096 + l) * 64 + c;
        g_Q[o] = e4(a0[j]);
        g_K[o] = e4(a1[j]);
    }

    // V transpose through smem, then fp8 + sigma permutation on key bytes
    __syncthreads();
    __nv_bfloat16* vt = &Ws[0][0][0];   // [64][72] overlay
    #pragma unroll
    for (int j = 0; j < 16; j++)
        vt[c * 72 + g * 16 + j] = __float2bfloat16(a2[j]);
    __syncthreads();
    {
        int c_out = tid >> 2;
        int lg    = (tid & 3) * 16;
        uint32_t w[4];
        #pragma unroll
        for (int k = 0; k < 4; k++) {
            // halfword hi covers permuted byte-pair; source keys l, l+1 with
            // l = ((hi&1)<<3) | (hi & 6)
            int hi0 = 2 * k, hi1 = 2 * k + 1;
            int la = ((hi0 & 1) << 3) | (hi0 & 6);
            int lb = ((hi1 & 1) << 3) | (hi1 & 6);
            uint16_t h0 = pk_e4(__bfloat162float(vt[c_out * 72 + lg + la]),
                                __bfloat162float(vt[c_out * 72 + lg + la + 1]));
            uint16_t h1 = pk_e4(__bfloat162float(vt[c_out * 72 + lg + lb]),
                                __bfloat162float(vt[c_out * 72 + lg + lb + 1]));
            w[k] = (uint32_t)h0 | ((uint32_t)h1 << 16);
        }
        uint4* dst = reinterpret_cast<uint4*>(
            g_V + (size_t)(b * 64 + c_out) * 4096 + l0 + lg);
        *dst = make_uint4(w[0], w[1], w[2], w[3]);
    }
}

// ---------------------------------------------------------------------------
// Kernel B: FP8 FlashAttention (Br=128 over 8 warps, Bc=64, d=64).
// S raw = Q K^T (fp8); p = exp2(S * log2e/64) f32; P fp8 regs -> PV (fp8).
// out[b,c,l] = gamma * (softmax V)[l,c] + x[b,c,l]
// ---------------------------------------------------------------------------
// smem: Q [128][64B] @0 (8KB); K 3 stages x [64][64B] @8192; V 3 x [64][64B] @20480.
// epilogue overlay: [64][132] f32 (33792 B)
__global__ void __launch_bounds__(256, 2) attn_kernel(
    const float* __restrict__ x,
    const float* __restrict__ gamma,
    float* __restrict__ out)
{
    __shared__ __align__(16) unsigned char smem[33792];
    const int b    = blockIdx.x >> 5;
    const int q0   = (blockIdx.x & 31) * BR;
    const int tid  = threadIdx.x;
    const int lane = tid & 31;
    const int warp = tid >> 5;

    const uint32_t qs = smem_u32(smem);
    const uint32_t ks = qs + 8192;
    const uint32_t vs = qs + 20480;

    const uint8_t* Qg = g_Q + ((size_t)b * L + q0) * C;
    const uint8_t* Kg = g_K + (size_t)b * L * C;
    const uint8_t* Vg = g_V + (size_t)b * C * L;

    // Prologue: group A = Q + stage0, group B = stage1
    for (int i = tid; i < 512; i += 256) {
        int r = i >> 2, ck = i & 3;
        cp16(qs + swz64(r * 64 + ck * 16), Qg + r * 64 + ck * 16);
    }
    for (int i = tid; i < 256; i += 256) {
        int r = i >> 2, ck = i & 3;
        cp16(ks + swz64(r * 64 + ck * 16), Kg + r * 64 + ck * 16);
    }
    for (int i = tid; i < 256; i += 256) {
        int cch = i >> 2, ck = i & 3;
        cp16(vs + swz64(cch * 64 + ck * 16), Vg + (size_t)cch * L + ck * 16);
    }
    cp_commit();
    {
        const uint8_t* K1 = Kg + (size_t)BC * C;
        const uint8_t* V1 = Vg;   // V keys offset = BC bytes along L
        for (int i = tid; i < 256; i += 256) {
            int r = i >> 2, ck = i & 3;
            cp16(ks + 4096 + swz64(r * 64 + ck * 16), K1 + r * 64 + ck * 16);
        }
        for (int i = tid; i < 256; i += 256) {
            int cch = i >> 2, ck = i & 3;
            cp16(vs + 4096 + swz64(cch * 64 + ck * 16), V1 + (size_t)cch * L + BC + ck * 16);
        }
        cp_commit();
    }
    cp_wait<1>();
    __syncthreads();

    // Q A-fragments: [kt 0..1][4 regs]; rows = this warp's 16, k = 64 channel-bytes
    uint32_t qa[2][4];
    {
        const int wr = warp * 16;
        const int m  = lane >> 3;
        #pragma unroll
        for (int kt = 0; kt < 2; kt++) {
            int row = wr + (lane & 7) + (m & 1) * 8;
            int chb = kt * 32 + (m >> 1) * 16;
            ldsm_x4(qa[kt][0], qa[kt][1], qa[kt][2], qa[kt][3],
                    qs + swz64(row * 64 + chb));
        }
    }

    float lpart[2] = {0.f, 0.f};
    float o[8][4];
    #pragma unroll
    for (int ct = 0; ct < 8; ct++)
        #pragma unroll
        for (int e = 0; e < 4; e++) o[ct][e] = 0.f;

    const int krow = (lane & 7) + ((lane >> 4) & 1) * 8;   // + j*16
    const int kch  = (lane >> 3) & 1;                      // 16B half within 32B k-chunk
    const float SC = 1.4426950408889634f / 64.f;

    for (int it = 0; it < NIT; it++) {
        // Prefetch stage it+2 into buffer (it+2)%3
        if (it + 2 < NIT) {
            int nb = (it + 2) % 3;
            const uint8_t* Kn = Kg + (size_t)(it + 2) * BC * C;
            for (int i = tid; i < 256; i += 256) {
                int r = i >> 2, ck = i & 3;
                cp16(ks + nb * 4096 + swz64(r * 64 + ck * 16), Kn + r * 64 + ck * 16);
            }
            for (int i = tid; i < 256; i += 256) {
                int cch = i >> 2, ck = i & 3;
                cp16(vs + nb * 4096 + swz64(cch * 64 + ck * 16),
                     Vg + (size_t)cch * L + (size_t)(it + 2) * BC + ck * 16);
            }
            cp_commit();
        }

        const uint32_t kbase = ks + (it % 3) * 4096;
        const uint32_t vbase = vs + (it % 3) * 4096;

        // S = Q K^T (raw fp8 dot products, f32 accum)
        float s[8][4];
        #pragma unroll
        for (int nt = 0; nt < 8; nt++)
            #pragma unroll
            for (int e = 0; e < 4; e++) s[nt][e] = 0.f;

        #pragma unroll
        for (int kt = 0; kt < 2; kt++) {
            #pragma unroll
            for (int j = 0; j < 4; j++) {
                uint32_t b0, b1, b2, b3;
                int row = j * 16 + krow;
                int chb = kt * 32 + kch * 16;
                ldsm_x4(b0, b1, b2, b3, kbase + swz64(row * 64 + chb));
                mma_fp8(s[2*j][0], s[2*j][1], s[2*j][2], s[2*j][3],
                        qa[kt][0], qa[kt][1], qa[kt][2], qa[kt][3], b0, b1);
                mma_fp8(s[2*j+1][0], s[2*j+1][1], s[2*j+1][2], s[2*j+1][3],
                        qa[kt][0], qa[kt][1], qa[kt][2], qa[kt][3], b2, b3);
            }
        }

        // p = exp2(s * SC); accumulate row-sums; pack into PV A-fragments.
        // Thanks to the sigma permutation on V's key bytes, lane-local packing
        // [nt c0,c1 | nt+1 c0,c1] is exactly the m16n8k32 A layout.
        float p[8][4];
        #pragma unroll
        for (int nt = 0; nt < 8; nt++) {
            p[nt][0] = fast_exp2(s[nt][0] * SC);
            p[nt][1] = fast_exp2(s[nt][1] * SC);
            p[nt][2] = fast_exp2(s[nt][2] * SC);
            p[nt][3] = fast_exp2(s[nt][3] * SC);
            lpart[0] += p[nt][0] + p[nt][1];
            lpart[1] += p[nt][2] + p[nt][3];
        }
        uint32_t pa[2][4];
        #pragma unroll
        for (int kt = 0; kt < 2; kt++) {
            int n0 = 4 * kt;
            pa[kt][0] = (uint32_t)pk_e4(p[n0][0],   p[n0][1])
                      | ((uint32_t)pk_e4(p[n0+1][0], p[n0+1][1]) << 16);
            pa[kt][1] = (uint32_t)pk_e4(p[n0][2],   p[n0][3])
                      | ((uint32_t)pk_e4(p[n0+1][2], p[n0+1][3]) << 16);
            pa[kt][2] = (uint32_t)pk_e4(p[n0+2][0], p[n0+2][1])
                      | ((uint32_t)pk_e4(p[n0+3][0], p[n0+3][1]) << 16);
            pa[kt][3] = (uint32_t)pk_e4(p[n0+2][2], p[n0+2][3])
                      | ((uint32_t)pk_e4(p[n0+3][2], p[n0+3][3]) << 16);
        }

        // O += P V   (V smem rows = channels, k-bytes = permuted keys)
        #pragma unroll
        for (int kt = 0; kt < 2; kt++) {
            #pragma unroll
            for (int j = 0; j < 4; j++) {
                uint32_t v0, v1, v2, v3;
                int row = j * 16 + krow;          // channel rows
                int chb = kt * 32 + kch * 16;     // key-byte chunk
                ldsm_x4(v0, v1, v2, v3, vbase + swz64(row * 64 + chb));
                mma_fp8(o[2*j][0], o[2*j][1], o[2*j][2], o[2*j][3],
                        pa[kt][0], pa[kt][1], pa[kt][2], pa[kt][3], v0, v1);
                mma_fp8(o[2*j+1][0], o[2*j+1][1], o[2*j+1][2], o[2*j+1][3],
                        pa[kt][0], pa[kt][1], pa[kt][2], pa[kt][3], v2, v3);
            }
        }

        if (it + 1 < NIT) {
            if (it + 2 < NIT) cp_wait<1>(); else cp_wait<0>();
            __syncthreads();
        }
    }

    // Row-sum reduction across the 4 lanes sharing each row
    #pragma unroll
    for (int h = 0; h < 2; h++) {
        lpart[h] += __shfl_xor_sync(0xffffffffu, lpart[h], 1);
        lpart[h] += __shfl_xor_sync(0xffffffffu, lpart[h], 2);
    }
    float inv[2] = { fast_rcp(lpart[0]), fast_rcp(lpart[1]) };

    // Epilogue: normalize, transpose through smem, fused residual write
    __syncthreads();
    float* Os = (float*)smem;   // [64][132]

    const int wr = warp * 16;
    #pragma unroll
    for (int h = 0; h < 2; h++) {
        int row  = wr + h * 8 + (lane >> 2);
        float iv = inv[h];
        #pragma unroll
        for (int ct = 0; ct < 8; ct++) {
            int c0 = ct * 8 + 2 * (lane & 3);
            Os[c0 * 132 + row]       = o[ct][2 * h]     * iv;
            Os[(c0 + 1) * 132 + row] = o[ct][2 * h + 1] * iv;
        }
    }
    __syncthreads();

    const float gam = gamma[0];
    for (int idx = tid; idx < 64 * 128; idx += 256) {
        int c = idx >> 7, j = idx & 127;
        size_t gi = ((size_t)(b * 64 + c)) * 4096 + q0 + j;
        out[gi] = gam * Os[c * 132 + j] + x[gi];
    }
}

// ---------------------------------------------------------------------------
extern "C" void kernel_launch(void* const* d_in, const int* in_sizes, int n_in,
                              void* d_out, int out_size) {
    (void)in_sizes; (void)n_in; (void)out_size;
    const float* x     = (const float*)d_in[0];
    const float* Wq    = (const float*)d_in[1];
    const float* bq    = (const float*)d_in[2];
    const float* Wk    = (const float*)d_in[3];
    const float* bk    = (const float*)d_in[4];
    const float* Wv    = (const float*)d_in[5];
    const float* bv    = (const float*)d_in[6];
    const float* gamma = (const float*)d_in[7];
    float* out = (float*)d_out;

    qkv_kernel<<<NB * (L / 64), 256>>>(x, Wq, bq, Wk, bk, Wv, bv);
    attn_kernel<<<NB * (L / BR), 256>>>(x, gamma, out);
}